// round 7
// baseline (speedup 1.0000x reference)
#include <cuda_runtime.h>
#include <stdint.h>
#include <math.h>

// ---------------- problem dims ----------------
#define NFEAT  6
#define PAIRS  15
#define EMBED  256
#define TOKENS 16384          // B*S
#define KCAT   512            // 2*EMBED

// ---------------- CTA tiling ----------------
// grid = TOKENS/32 = 512 CTAs, 256 threads (8 warps), warp grid 1x8
// warp tile 32(m) x 32(n): 2 m16-tiles x 4 n8-tiles of m16n8k8 tf32 mma
// __launch_bounds__(256,2): 2 CTAs/SM for latency hiding.
#define BM 32
#define BN 256

// ---------------- smem layout (u32 units) ----------------
#define ASTR 40               // A/H k-row stride (32 cols + 8 pad)
#define BSTR 264              // B k-row stride (256 cols + 8 pad)
#define AS_BUF (16 * ASTR)    // 640 u32
#define BS_BUF (16 * BSTR)    // 4224 u32
#define NBUF_B 3
#define OFF_AS 0
#define OFF_BS (2 * AS_BUF)                 // 1280
#define OFF_HS (OFF_BS + NBUF_B * BS_BUF)   // 1280 + 12672 = 13952
#define SMEM_U32 (OFF_HS + 256 * ASTR)      // 13952 + 10240 = 24192
#define SMEM_BYTES (SMEM_U32 * 4)           // 96768 B -> 2 CTAs/SM fits

// total B tiles per pair: 32 (stage1) + 16 (stage2)
#define NT_S1 32
#define NT_ALL 48

__device__ float g_Wp[(size_t)PAIRS * KCAT * EMBED];   // tf32-rounded (active pairs only)
__device__ float g_Wf[(size_t)PAIRS * EMBED * EMBED];  // tf32-rounded (active chunks only)

__constant__ int c_pi[PAIRS] = {0,0,0,0,0,1,1,1,1,2,2,2,3,3,4};
__constant__ int c_pj[PAIRS] = {1,2,3,4,5,2,3,4,5,3,4,5,4,5,5};

// ---------------- helpers ----------------
__device__ __forceinline__ uint32_t f2tf(float x) {
    uint32_t u; asm("cvt.rn.tf32.f32 %0, %1;" : "=r"(u) : "f"(x)); return u;
}
__device__ __forceinline__ float f2tf_f(float x) { return __uint_as_float(f2tf(x)); }
__device__ __forceinline__ float fast_tanh(float x) {
    float ax = fabsf(x);
    float e; asm("ex2.approx.f32 %0, %1;" : "=f"(e) : "f"(-2.8853900817779268f * ax));
    float d; asm("rcp.approx.f32 %0, %1;" : "=f"(d) : "f"(1.0f + e));
    float t = (1.0f - e) * d;
    return copysignf(t, x);
}
__device__ __forceinline__ uint32_t smem_u32(const void* p) {
    uint32_t a;
    asm("{ .reg .u64 t; cvta.to.shared.u64 t, %1; cvt.u32.u64 %0, t; }" : "=r"(a) : "l"(p));
    return a;
}
__device__ __forceinline__ void mma_tf32(float* c, const uint32_t* a, const uint32_t* b) {
    asm volatile(
        "mma.sync.aligned.m16n8k8.row.col.f32.tf32.tf32.f32 "
        "{%0,%1,%2,%3}, {%4,%5,%6,%7}, {%8,%9}, {%0,%1,%2,%3};\n"
        : "+f"(c[0]), "+f"(c[1]), "+f"(c[2]), "+f"(c[3])
        : "r"(a[0]), "r"(a[1]), "r"(a[2]), "r"(a[3]), "r"(b[0]), "r"(b[1]));
}
__device__ __forceinline__ int pair_active(int p, const int* __restrict__ NAS) {
    const int fi = c_pi[p], fj = c_pj[p];
    return ((fi < 2) ? 1 : NAS[fi]) * ((fj < 2) ? 1 : NAS[fj]);
}

#define CP16(dst, src) asm volatile("cp.async.cg.shared.global [%0], [%1], 16;" :: "r"(dst), "l"(src))
#define CP_COMMIT()    asm volatile("cp.async.commit_group;" ::: "memory")
#define CP_WAIT1()     asm volatile("cp.async.wait_group 1;" ::: "memory")
#define CP_WAIT0()     asm volatile("cp.async.wait_group 0;" ::: "memory")

// 16 k-steps of mma; bufA rows stride ASTR (swizzled cols mod 32), bufB stride BSTR.
__device__ __forceinline__ void tile_mma(const uint32_t* __restrict__ bufA,
                                         const uint32_t* __restrict__ bufB,
                                         int tig, int g, int wn,
                                         float acc[2][4][4]) {
    #pragma unroll
    for (int ks8 = 0; ks8 < 2; ks8++) {
        const int ks = ks8 * 8;
        const uint32_t* Ak0 = bufA + (ks + tig) * ASTR;
        const uint32_t* Ak4 = bufA + (ks + tig + 4) * ASTR;
        const int o0 = ks << 1;
        const int o4 = (ks << 1) + 8;
        uint32_t a[2][4];
        #pragma unroll
        for (int mi = 0; mi < 2; mi++) {
            const int m = mi * 16 + g;
            a[mi][0] = Ak0[(m + o0) & 31];
            a[mi][1] = Ak0[(m + 8 + o0) & 31];
            a[mi][2] = Ak4[(m + o4) & 31];
            a[mi][3] = Ak4[(m + 8 + o4) & 31];
        }
        const uint32_t* Bk0 = bufB + (ks + tig) * BSTR + wn + g;
        const uint32_t* Bk4 = bufB + (ks + tig + 4) * BSTR + wn + g;
        uint32_t b[4][2];
        #pragma unroll
        for (int ni = 0; ni < 4; ni++) { b[ni][0] = Bk0[ni * 8]; b[ni][1] = Bk4[ni * 8]; }
        #pragma unroll
        for (int mi = 0; mi < 2; mi++)
            #pragma unroll
            for (int ni = 0; ni < 4; ni++)
                mma_tf32(acc[mi][ni], a[mi], b[ni]);
    }
}

// ---------------- prep: round ACTIVE pairs' weights to tf32 ----------------
__global__ void prep_w_kernel(const float* __restrict__ Wp, const float* __restrict__ Wf,
                              const int* __restrict__ NAS) {
    const int p = blockIdx.y;
    if (!pair_active(p, NAS)) return;
    const int bx = blockIdx.x;
    if (bx < 64) {   // W_pair chunk: 512*256 floats = 32768 float4, 64 blocks x 256 thr x 2
        const float4* src = (const float4*)(Wp + (size_t)p * KCAT * EMBED);
        float4* dst = (float4*)(g_Wp + (size_t)p * KCAT * EMBED);
        #pragma unroll
        for (int q = 0; q < 2; q++) {
            int i = bx * 512 + q * 256 + threadIdx.x;
            float4 v = src[i];
            v.x = f2tf_f(v.x); v.y = f2tf_f(v.y); v.z = f2tf_f(v.z); v.w = f2tf_f(v.w);
            dst[i] = v;
        }
    } else {         // W_final chunk: 256*256 = 16384 float4, 16 blocks x 256 thr x 4
        const float4* src = (const float4*)(Wf + (size_t)p * EMBED * EMBED);
        float4* dst = (float4*)(g_Wf + (size_t)p * EMBED * EMBED);
        #pragma unroll
        for (int q = 0; q < 4; q++) {
            int i = (bx - 64) * 1024 + q * 256 + threadIdx.x;
            float4 v = src[i];
            v.x = f2tf_f(v.x); v.y = f2tf_f(v.y); v.z = f2tf_f(v.z); v.w = f2tf_f(v.w);
            dst[i] = v;
        }
    }
}

// ---------------- fused kernel ----------------
__global__ __launch_bounds__(256, 2) void fused_kernel(
    const float* __restrict__ features,
    const float* __restrict__ b_pair,
    const float* __restrict__ b_final,
    const int* __restrict__ NAS,
    float* __restrict__ out)
{
    extern __shared__ uint32_t sm[];
    uint32_t* const smA = sm + OFF_AS;
    uint32_t* const smB = sm + OFF_BS;
    uint32_t* const Hs  = sm + OFF_HS;
    const uint32_t smB_addr = smem_u32(smB);

    const int tid = threadIdx.x;
    const int lane = tid & 31, wid = tid >> 5;
    const int g = lane >> 2, tig = lane & 3;
    const int wn = wid * 32;
    const int row0 = blockIdx.x * BM;

    // A loader (tid<128): 32x16 tile, 1 float4/thread, swizzled transposed store
    const int a_row = tid >> 2;            // 0..63 (only <32 used)
    const int a_kb  = (tid & 3) * 4;       // 0,4,8,12
    const int a_col = (a_row + 2 * a_kb) & 31;
    const bool a_ld = tid < 128;

    // B loader: 16x256 tile; row = tid>>4, 64B contiguous per thread
    const int b_row  = tid >> 4;           // 0..15
    const int b_fcol = (tid & 15) * 16;    // float col 0..240
    const uint32_t b_dst_off = (uint32_t)(b_row * BSTR + b_fcol) * 4u;

#define STORE_A(bufp, v) do { \
        if (a_ld) { \
            uint32_t* d_ = (bufp) + a_kb * ASTR + a_col; \
            d_[0 * ASTR] = f2tf((v).x); d_[1 * ASTR] = f2tf((v).y); \
            d_[2 * ASTR] = f2tf((v).z); d_[3 * ASTR] = f2tf((v).w); \
        } \
    } while (0)
#define ISSUE_B(srcbase, t) do { \
        const float* s_ = (srcbase) + (size_t)b_row * EMBED + b_fcol; \
        uint32_t d_ = smB_addr + ((t) % NBUF_B) * (BS_BUF * 4u) + b_dst_off; \
        CP16(d_ + 0,  s_ + 0);  CP16(d_ + 16, s_ + 4); \
        CP16(d_ + 32, s_ + 8);  CP16(d_ + 48, s_ + 12); \
        CP_COMMIT(); \
    } while (0)

    float oacc[2][4][4];
    #pragma unroll
    for (int mi = 0; mi < 2; mi++)
        #pragma unroll
        for (int ni = 0; ni < 4; ni++)
            #pragma unroll
            for (int r = 0; r < 4; r++) oacc[mi][ni][r] = 0.f;

    #pragma unroll 1
    for (int p = 0; p < PAIRS; p++) {
        if (!pair_active(p, NAS)) continue;
        const int fi = c_pi[p], fj = c_pj[p];
        const float* Ai = features + ((size_t)fi * TOKENS + row0) * EMBED;
        const float* Aj = features + ((size_t)fj * TOKENS + row0) * EMBED;
        const float* Wp = g_Wp + (size_t)p * KCAT * EMBED;
        const float* Wf = g_Wf + (size_t)p * EMBED * EMBED;

        float hacc[2][4][4];
        #pragma unroll
        for (int mi = 0; mi < 2; mi++)
            #pragma unroll
            for (int ni = 0; ni < 4; ni++)
                #pragma unroll
                for (int r = 0; r < 4; r++) hacc[mi][ni][r] = 0.f;

        // ---- prologue ----
        float4 av;
        if (a_ld) av = *(const float4*)&Ai[(size_t)a_row * EMBED + a_kb];
        ISSUE_B(Wp, 0);
        ISSUE_B(Wp + 16 * EMBED, 1);
        STORE_A(smA, av);
        if (a_ld) av = *(const float4*)&Ai[(size_t)a_row * EMBED + 16 + a_kb];
        CP_WAIT1();
        __syncthreads();

        // ---- stage 1: 32 k-tiles; B pipeline spans all 48 tiles ----
        #pragma unroll 1
        for (int t = 0; t < NT_S1; t++) {
            tile_mma(smA + (t & 1) * AS_BUF, smB + (t % NBUF_B) * BS_BUF, tig, g, wn, hacc);
            if (t + 1 < NT_S1) STORE_A(smA + ((t + 1) & 1) * AS_BUF, av);
            if (t + 2 < NT_S1 && a_ld) {
                const int k2 = t + 2;
                const float* Ab = (k2 < 16) ? Ai : Aj;
                av = *(const float4*)&Ab[(size_t)a_row * EMBED + (k2 & 15) * 16 + a_kb];
            }
            {   // next B tile (stage-1 or stage-2 source)
                const int u = t + 2;
                if (u < NT_S1)       ISSUE_B(Wp + (size_t)u * 16 * EMBED, u);
                else if (u < NT_ALL) ISSUE_B(Wf + (size_t)(u - NT_S1) * 16 * EMBED, u);
            }
            CP_WAIT1();
            __syncthreads();
        }

        // ---- epilogue 1: tanh -> tf32 -> Hs (stage-2 A layout, swizzled) ----
        #pragma unroll
        for (int ni = 0; ni < 4; ni++) {
            const int c = wn + ni * 8 + tig * 2;
            const float2 bb = *(const float2*)&b_pair[p * EMBED + c];
            const int sw = 2 * (c & 12);   // same for c and c+1
            #pragma unroll
            for (int mi = 0; mi < 2; mi++) {
                const int r0 = mi * 16 + g, r1 = r0 + 8;
                Hs[(c    ) * ASTR + ((r0 + sw) & 31)] = f2tf(fast_tanh(hacc[mi][ni][0] + bb.x));
                Hs[(c + 1) * ASTR + ((r0 + sw) & 31)] = f2tf(fast_tanh(hacc[mi][ni][1] + bb.y));
                Hs[(c    ) * ASTR + ((r1 + sw) & 31)] = f2tf(fast_tanh(hacc[mi][ni][2] + bb.x));
                Hs[(c + 1) * ASTR + ((r1 + sw) & 31)] = f2tf(fast_tanh(hacc[mi][ni][3] + bb.y));
            }
        }
        __syncthreads();

        // ---- stage 2: 16 k-tiles from Hs; B pipeline continues ----
        #pragma unroll 1
        for (int s = 0; s < 16; s++) {
            const int t = NT_S1 + s;
            tile_mma(Hs + s * 16 * ASTR, smB + (t % NBUF_B) * BS_BUF, tig, g, wn, oacc);
            if (t + 2 < NT_ALL) {
                ISSUE_B(Wf + (size_t)(s + 2) * 16 * EMBED, t + 2);
                CP_WAIT1();
            } else {
                CP_WAIT0();
            }
            __syncthreads();
        }
    }

    // ---- final epilogue ----
    #pragma unroll
    for (int ni = 0; ni < 4; ni++) {
        const int c = wn + ni * 8 + tig * 2;
        const float2 bb = *(const float2*)&b_final[c];
        #pragma unroll
        for (int mi = 0; mi < 2; mi++) {
            const int r0 = row0 + mi * 16 + g, r1 = r0 + 8;
            float2 v0 = make_float2(oacc[mi][ni][0] + bb.x, oacc[mi][ni][1] + bb.y);
            float2 v1 = make_float2(oacc[mi][ni][2] + bb.x, oacc[mi][ni][3] + bb.y);
            *(float2*)&out[(size_t)r0 * EMBED + c] = v0;
            *(float2*)&out[(size_t)r1 * EMBED + c] = v1;
        }
    }
#undef STORE_A
#undef ISSUE_B
}

// ---------------- launch ----------------
extern "C" void kernel_launch(void* const* d_in, const int* in_sizes, int n_in,
                              void* d_out, int out_size) {
    const float* features = (const float*)d_in[0];
    const float* W_pair   = (const float*)d_in[1];
    const float* b_pair   = (const float*)d_in[2];
    const float* W_final  = (const float*)d_in[3];
    const float* b_final  = (const float*)d_in[4];
    const int*   NAS      = (const int*)d_in[5];
    float* out = (float*)d_out;

    static int attr_set = 0;
    if (!attr_set) {
        cudaFuncSetAttribute(fused_kernel, cudaFuncAttributeMaxDynamicSharedMemorySize,
                             SMEM_BYTES);
        attr_set = 1;
    }

    prep_w_kernel<<<dim3(80, PAIRS), 256>>>(W_pair, W_final, NAS);
    fused_kernel<<<TOKENS / BM, 256, SMEM_BYTES>>>(features, b_pair, b_final, NAS, out);
}

// round 8
// speedup vs baseline: 1.5291x; 1.5291x over previous
#include <cuda_runtime.h>
#include <stdint.h>
#include <math.h>

// ---------------- problem dims ----------------
#define NFEAT  6
#define PAIRS  15
#define EMBED  256
#define TOKENS 16384          // B*S
#define KCAT   512            // 2*EMBED

// ---------------- CTA tiling ----------------
// grid = TOKENS/64 = 256 CTAs, 512 threads (16 warps), warp grid 2(m) x 8(n)
// warp tile 32(m) x 32(n): 2 m16-tiles x 4 n8-tiles of m16n8k8 tf32 mma
// hacc+oacc = 32+32 floats/thread -> ~115 regs -> full regfile at 512 thr, 16 warps/SM.
#define BM 64
#define BN 256

// ---------------- smem layout (u32 units) ----------------
#define ASTR 72               // A/H k-row stride (64 cols + 8 pad); 72 % 32 == 8
#define BSTR 264              // B k-row stride (256 cols + 8 pad); 264 % 32 == 8
#define AS_BUF (16 * ASTR)    // 1152 u32
#define BS_BUF (16 * BSTR)    // 4224 u32
#define NBUF_B 3
#define OFF_AS 0
#define OFF_BS (2 * AS_BUF)                 // 2304
#define OFF_HS (OFF_BS + NBUF_B * BS_BUF)   // 2304 + 12672 = 14976
#define SMEM_U32 (OFF_HS + 256 * ASTR)      // 14976 + 18432 = 33408
#define SMEM_BYTES (SMEM_U32 * 4)           // 133632 B (1 CTA/SM)

#define NT_S1 32              // stage-1 k-tiles (K=512)
#define NT_ALL 48             // + 16 stage-2 k-tiles (K=256)

__device__ float g_Wp[(size_t)PAIRS * KCAT * EMBED];   // tf32-rounded (active pairs only)
__device__ float g_Wf[(size_t)PAIRS * EMBED * EMBED];  // tf32-rounded (active chunks only)

__constant__ int c_pi[PAIRS] = {0,0,0,0,0,1,1,1,1,2,2,2,3,3,4};
__constant__ int c_pj[PAIRS] = {1,2,3,4,5,2,3,4,5,3,4,5,4,5,5};

// ---------------- helpers ----------------
__device__ __forceinline__ uint32_t f2tf(float x) {
    uint32_t u; asm("cvt.rn.tf32.f32 %0, %1;" : "=r"(u) : "f"(x)); return u;
}
__device__ __forceinline__ float f2tf_f(float x) { return __uint_as_float(f2tf(x)); }
__device__ __forceinline__ float fast_tanh(float x) {
    float ax = fabsf(x);
    float e; asm("ex2.approx.f32 %0, %1;" : "=f"(e) : "f"(-2.8853900817779268f * ax));
    float d; asm("rcp.approx.f32 %0, %1;" : "=f"(d) : "f"(1.0f + e));
    float t = (1.0f - e) * d;
    return copysignf(t, x);
}
__device__ __forceinline__ uint32_t smem_u32(const void* p) {
    uint32_t a;
    asm("{ .reg .u64 t; cvta.to.shared.u64 t, %1; cvt.u32.u64 %0, t; }" : "=r"(a) : "l"(p));
    return a;
}
__device__ __forceinline__ void mma_tf32(float* c, const uint32_t* a, const uint32_t* b) {
    asm volatile(
        "mma.sync.aligned.m16n8k8.row.col.f32.tf32.tf32.f32 "
        "{%0,%1,%2,%3}, {%4,%5,%6,%7}, {%8,%9}, {%0,%1,%2,%3};\n"
        : "+f"(c[0]), "+f"(c[1]), "+f"(c[2]), "+f"(c[3])
        : "r"(a[0]), "r"(a[1]), "r"(a[2]), "r"(a[3]), "r"(b[0]), "r"(b[1]));
}
__device__ __forceinline__ int pair_active(int p, const int* __restrict__ NAS) {
    const int fi = c_pi[p], fj = c_pj[p];
    return ((fi < 2) ? 1 : NAS[fi]) * ((fj < 2) ? 1 : NAS[fj]);
}

#define CP16(dst, src) asm volatile("cp.async.cg.shared.global [%0], [%1], 16;" :: "r"(dst), "l"(src))
#define CP_COMMIT()    asm volatile("cp.async.commit_group;" ::: "memory")
#define CP_WAIT1()     asm volatile("cp.async.wait_group 1;" ::: "memory")
#define CP_WAIT0()     asm volatile("cp.async.wait_group 0;" ::: "memory")

// 16 k-steps of one BK-tile; A rows stride ASTR (cols swizzled mod 64), B stride BSTR.
__device__ __forceinline__ void tile_mma(const uint32_t* __restrict__ bufA,
                                         const uint32_t* __restrict__ bufB,
                                         int tig, int g, int wm, int wn,
                                         float acc[2][4][4]) {
    #pragma unroll
    for (int ks8 = 0; ks8 < 2; ks8++) {
        const int ks = ks8 * 8;
        const uint32_t* Ak0 = bufA + (ks + tig) * ASTR;
        const uint32_t* Ak4 = bufA + (ks + tig + 4) * ASTR;
        const int o0 = ks << 1;
        const int o4 = (ks << 1) + 8;
        uint32_t a[2][4];
        #pragma unroll
        for (int mi = 0; mi < 2; mi++) {
            const int m = wm + mi * 16 + g;
            a[mi][0] = Ak0[(m + o0) & 63];
            a[mi][1] = Ak0[(m + 8 + o0) & 63];
            a[mi][2] = Ak4[(m + o4) & 63];
            a[mi][3] = Ak4[(m + 8 + o4) & 63];
        }
        const uint32_t* Bk0 = bufB + (ks + tig) * BSTR + wn + g;
        const uint32_t* Bk4 = bufB + (ks + tig + 4) * BSTR + wn + g;
        uint32_t b[4][2];
        #pragma unroll
        for (int ni = 0; ni < 4; ni++) { b[ni][0] = Bk0[ni * 8]; b[ni][1] = Bk4[ni * 8]; }
        #pragma unroll
        for (int mi = 0; mi < 2; mi++)
            #pragma unroll
            for (int ni = 0; ni < 4; ni++)
                mma_tf32(acc[mi][ni], a[mi], b[ni]);
    }
}

// ---------------- prep: round ACTIVE pairs' weights to tf32 ----------------
__global__ void prep_w_kernel(const float* __restrict__ Wp, const float* __restrict__ Wf,
                              const int* __restrict__ NAS) {
    const int p = blockIdx.y;
    if (!pair_active(p, NAS)) return;
    const int bx = blockIdx.x;
    if (bx < 64) {   // W_pair chunk: 512*256 floats = 32768 float4
        const float4* src = (const float4*)(Wp + (size_t)p * KCAT * EMBED);
        float4* dst = (float4*)(g_Wp + (size_t)p * KCAT * EMBED);
        #pragma unroll
        for (int q = 0; q < 2; q++) {
            int i = bx * 512 + q * 256 + threadIdx.x;
            float4 v = src[i];
            v.x = f2tf_f(v.x); v.y = f2tf_f(v.y); v.z = f2tf_f(v.z); v.w = f2tf_f(v.w);
            dst[i] = v;
        }
    } else {         // W_final chunk: 256*256 floats = 16384 float4
        const float4* src = (const float4*)(Wf + (size_t)p * EMBED * EMBED);
        float4* dst = (float4*)(g_Wf + (size_t)p * EMBED * EMBED);
        #pragma unroll
        for (int q = 0; q < 4; q++) {
            int i = (bx - 64) * 1024 + q * 256 + threadIdx.x;
            float4 v = src[i];
            v.x = f2tf_f(v.x); v.y = f2tf_f(v.y); v.z = f2tf_f(v.z); v.w = f2tf_f(v.w);
            dst[i] = v;
        }
    }
}

// ---------------- fused kernel (512 threads) ----------------
__global__ __launch_bounds__(512, 1) void fused_kernel(
    const float* __restrict__ features,
    const float* __restrict__ b_pair,
    const float* __restrict__ b_final,
    const int* __restrict__ NAS,
    float* __restrict__ out)
{
    extern __shared__ uint32_t sm[];
    uint32_t* const smA = sm + OFF_AS;
    uint32_t* const smB = sm + OFF_BS;
    uint32_t* const Hs  = sm + OFF_HS;
    const uint32_t smB_addr = smem_u32(smB);

    const int tid = threadIdx.x;
    const int lane = tid & 31, wid = tid >> 5;
    const int g = lane >> 2, tig = lane & 3;
    const int wm = (wid >> 3) * 32;     // 2 m-blocks
    const int wn = (wid & 7) * 32;      // 8 n-blocks
    const int row0 = blockIdx.x * BM;

    // A loader (tid<256): 64x16 tile, 1 float4/thread, swizzled transposed STS
    const int a_row = tid >> 2;            // 0..63 (tid<256)
    const int a_kb  = (tid & 3) * 4;       // 0,4,8,12
    const int a_col = (a_row + 2 * a_kb) & 63;
    const bool a_ld = tid < 256;

    // B loader (all 512): 16x256 tile, 32B/thread
    const int b_row  = tid >> 5;           // 0..15
    const int b_fcol = (tid & 31) * 8;     // float col, step 8
    const uint32_t b_dst_off = (uint32_t)(b_row * BSTR + b_fcol) * 4u;

#define STORE_A(bufp, v) do { \
        if (a_ld) { \
            uint32_t* d_ = (bufp) + a_kb * ASTR + a_col; \
            d_[0 * ASTR] = f2tf((v).x); d_[1 * ASTR] = f2tf((v).y); \
            d_[2 * ASTR] = f2tf((v).z); d_[3 * ASTR] = f2tf((v).w); \
        } \
    } while (0)
#define ISSUE_B(srcbase, t) do { \
        const float* s_ = (srcbase) + (size_t)b_row * EMBED + b_fcol; \
        uint32_t d_ = smB_addr + ((t) % NBUF_B) * (BS_BUF * 4u) + b_dst_off; \
        CP16(d_, s_); CP16(d_ + 16, s_ + 4); \
        CP_COMMIT(); \
    } while (0)

    float oacc[2][4][4];
    #pragma unroll
    for (int mi = 0; mi < 2; mi++)
        #pragma unroll
        for (int ni = 0; ni < 4; ni++)
            #pragma unroll
            for (int r = 0; r < 4; r++) oacc[mi][ni][r] = 0.f;

    #pragma unroll 1
    for (int p = 0; p < PAIRS; p++) {
        if (!pair_active(p, NAS)) continue;
        const int fi = c_pi[p], fj = c_pj[p];
        const float* Ai = features + ((size_t)fi * TOKENS + row0) * EMBED;
        const float* Aj = features + ((size_t)fj * TOKENS + row0) * EMBED;
        const float* Wp = g_Wp + (size_t)p * KCAT * EMBED;
        const float* Wf = g_Wf + (size_t)p * EMBED * EMBED;

        float hacc[2][4][4];
        #pragma unroll
        for (int mi = 0; mi < 2; mi++)
            #pragma unroll
            for (int ni = 0; ni < 4; ni++)
                #pragma unroll
                for (int r = 0; r < 4; r++) hacc[mi][ni][r] = 0.f;

        // ---- prologue ----
        float4 av;
        if (a_ld) av = *(const float4*)&Ai[(size_t)a_row * EMBED + a_kb];
        ISSUE_B(Wp, 0);
        ISSUE_B(Wp + 16 * EMBED, 1);
        STORE_A(smA, av);
        if (a_ld) av = *(const float4*)&Ai[(size_t)a_row * EMBED + 16 + a_kb];
        CP_WAIT1();
        __syncthreads();

        // ---- stage 1: 32 k-tiles; B pipeline spans all 48 tiles ----
        #pragma unroll 1
        for (int t = 0; t < NT_S1; t++) {
            tile_mma(smA + (t & 1) * AS_BUF, smB + (t % NBUF_B) * BS_BUF,
                     tig, g, wm, wn, hacc);
            if (t + 1 < NT_S1) STORE_A(smA + ((t + 1) & 1) * AS_BUF, av);
            if (t + 2 < NT_S1 && a_ld) {
                const int k2 = t + 2;
                const float* Ab = (k2 < 16) ? Ai : Aj;
                av = *(const float4*)&Ab[(size_t)a_row * EMBED + (k2 & 15) * 16 + a_kb];
            }
            {
                const int u = t + 2;
                if (u < NT_S1)       ISSUE_B(Wp + (size_t)u * 16 * EMBED, u);
                else if (u < NT_ALL) ISSUE_B(Wf + (size_t)(u - NT_S1) * 16 * EMBED, u);
            }
            CP_WAIT1();
            __syncthreads();
        }

        // ---- epilogue 1: tanh -> tf32 -> Hs (stage-2 A layout, swizzled) ----
        #pragma unroll
        for (int ni = 0; ni < 4; ni++) {
            const int c = wn + ni * 8 + tig * 2;
            const float2 bb = *(const float2*)&b_pair[p * EMBED + c];
            const int sw = 2 * (c & 12);   // same for c and c+1
            #pragma unroll
            for (int mi = 0; mi < 2; mi++) {
                const int r0 = wm + mi * 16 + g, r1 = r0 + 8;
                Hs[(c    ) * ASTR + ((r0 + sw) & 63)] = f2tf(fast_tanh(hacc[mi][ni][0] + bb.x));
                Hs[(c + 1) * ASTR + ((r0 + sw) & 63)] = f2tf(fast_tanh(hacc[mi][ni][1] + bb.y));
                Hs[(c    ) * ASTR + ((r1 + sw) & 63)] = f2tf(fast_tanh(hacc[mi][ni][2] + bb.x));
                Hs[(c + 1) * ASTR + ((r1 + sw) & 63)] = f2tf(fast_tanh(hacc[mi][ni][3] + bb.y));
            }
        }
        __syncthreads();

        // ---- stage 2: 16 k-tiles from Hs; B pipeline continues ----
        #pragma unroll 1
        for (int s = 0; s < 16; s++) {
            const int t = NT_S1 + s;
            tile_mma(Hs + s * 16 * ASTR, smB + (t % NBUF_B) * BS_BUF,
                     tig, g, wm, wn, oacc);
            if (t + 2 < NT_ALL) {
                ISSUE_B(Wf + (size_t)(s + 2) * 16 * EMBED, t + 2);
                CP_WAIT1();
            } else {
                CP_WAIT0();
            }
            __syncthreads();
        }
    }

    // ---- final epilogue ----
    #pragma unroll
    for (int ni = 0; ni < 4; ni++) {
        const int c = wn + ni * 8 + tig * 2;
        const float2 bb = *(const float2*)&b_final[c];
        #pragma unroll
        for (int mi = 0; mi < 2; mi++) {
            const int r0 = row0 + wm + mi * 16 + g, r1 = r0 + 8;
            float2 v0 = make_float2(oacc[mi][ni][0] + bb.x, oacc[mi][ni][1] + bb.y);
            float2 v1 = make_float2(oacc[mi][ni][2] + bb.x, oacc[mi][ni][3] + bb.y);
            *(float2*)&out[(size_t)r0 * EMBED + c] = v0;
            *(float2*)&out[(size_t)r1 * EMBED + c] = v1;
        }
    }
#undef STORE_A
#undef ISSUE_B
}

// ---------------- launch ----------------
extern "C" void kernel_launch(void* const* d_in, const int* in_sizes, int n_in,
                              void* d_out, int out_size) {
    const float* features = (const float*)d_in[0];
    const float* W_pair   = (const float*)d_in[1];
    const float* b_pair   = (const float*)d_in[2];
    const float* W_final  = (const float*)d_in[3];
    const float* b_final  = (const float*)d_in[4];
    const int*   NAS      = (const int*)d_in[5];
    float* out = (float*)d_out;

    static int attr_set = 0;
    if (!attr_set) {
        cudaFuncSetAttribute(fused_kernel, cudaFuncAttributeMaxDynamicSharedMemorySize,
                             SMEM_BYTES);
        attr_set = 1;
    }

    prep_w_kernel<<<dim3(80, PAIRS), 256>>>(W_pair, W_final, NAS);
    fused_kernel<<<TOKENS / BM, 512, SMEM_BYTES>>>(features, b_pair, b_final, NAS, out);
}